// round 13
// baseline (speedup 1.0000x reference)
#include <cuda_runtime.h>

// HMLoss: 4-region histogram-matching L1 loss, H=W=2048.
// R13: ONE launch, role-split blocks running concurrently:
//   hist-role (185 blocks): 24 CDF histograms (proven body, 128MB read)
//   moment-role (111 blocks): per-(region,ch,floor-bin) cnt2/sum2 moments of
//     denorm(fake) over mask_A (64MB read) -- table-INDEPENDENT, so it runs
//     in parallel with hist instead of as a dependent 22.8us second kernel.
//   Loss closed form per bin: sum|v - tbl| = |sum2 - tbl*cnt2| (sign uniform
//   within a floor-bin since tbl is integer). Ticket -> last block builds
//   tables (R12 integer-exact tail) + reduces 3072 bins + writes out + cleans.

#define NQ    1048576   // (2048*2048)/4
#define NB    256
#define NHIST 24
#define GRID  296
#define NHB   185       // hist-role blocks  (bid%8 < 5)
#define NMB   111       // moment-role blocks

__device__ unsigned int g_hist[NHIST * NB];   // zeroed at load; self-cleaning
__device__ unsigned int g_cnt2[12 * NB];
__device__ float        g_sum2[12 * NB];
__device__ unsigned int g_tick;

// Packed label LUTs (labels 0..18).
// A: low16 = src hist base + 1 (0 = unmasked), bit16 = (label==11)
// B: low16 = tar hist base + 1 for hair/eye (0 = none), bit16 = in tar face set
__constant__ int c_lutA[32] = {
    0, 1, 3073, 4609, 3073, 4609, 0,
    1, 1, 0, 1, 1 | (1 << 16), 0, 0,
    1, 0, 0, 1537, 0,
    0,0,0,0,0,0,0,0,0,0,0,0,0
};
__constant__ int c_lutB[32] = {
    0, (1<<16), 3841, 5377, 3841, 5377, 0,
    (1<<16), (1<<16), 0, (1<<16), 0, 0, 0,
    (1<<16), 0, 0, 2305, 0,
    0,0,0,0,0,0,0,0,0,0,0,0,0
};

__device__ __forceinline__ int floor_pos(float x) {
    return __float_as_int(__fadd_rz(x, 8388608.0f)) & 0x7FFFFF;
}
__device__ __forceinline__ float sat01(float x) {
    return __saturatef(fmaf(x, 0.5f, 0.5f));
}

// ---------------- hist per-pixel (proven body) ----------------
__device__ __forceinline__ void hist_px(int la, int lb,
                                        float fa, float fb, float fc,
                                        float ra, float rb, float rc,
                                        const int* lutA, const int* lutB,
                                        unsigned int* sh)
{
    int da = lutA[la];
    int db = lutB[lb];

    int sbase = (da & 0xFFFF) - 1;
    if (sbase >= 0) {
        int b0 = min(floor_pos(sat01(fa) * 256.0f), 255);
        int b1 = min(floor_pos(sat01(fb) * 256.0f), 255);
        int b2 = min(floor_pos(sat01(fc) * 256.0f), 255);
        atomicAdd(&sh[sbase          + b0], 1u);
        atomicAdd(&sh[sbase +     NB + b1], 1u);
        atomicAdd(&sh[sbase + 2 * NB + b2], 1u);
    }

    int faceval = ((da >> 16) & 1) + ((db >> 16) & 1);
    int tbase = (db & 0xFFFF) - 1;
    if ((faceval | (tbase + 1)) != 0) {
        float scale = (faceval == 2) ? 512.0f : 256.0f;   // faceval==2 implies tbase<0
        int b0 = min(floor_pos(sat01(ra) * scale), 255);
        int b1 = min(floor_pos(sat01(rb) * scale), 255);
        int b2 = min(floor_pos(sat01(rc) * scale), 255);
        if (faceval > 0) {
            atomicAdd(&sh[3 * NB          + b0], 1u);
            atomicAdd(&sh[3 * NB +     NB + b1], 1u);
            atomicAdd(&sh[3 * NB + 2 * NB + b2], 1u);
        }
        if (tbase >= 0) {
            atomicAdd(&sh[tbase          + b0], 1u);
            atomicAdd(&sh[tbase +     NB + b1], 1u);
            atomicAdd(&sh[tbase + 2 * NB + b2], 1u);
        }
    }
}

// ---------------- moment per-pixel ----------------
__device__ __forceinline__ void mom_px(int la, float fa, float fb, float fc,
                                       const int* lutA,
                                       unsigned* s_cnt, float* s_sum)
{
    int base2 = ((lutA[la] & 0xFFFF) - 1) >> 1;   // region*3*NB
    if (base2 >= 0) {
        float v0 = sat01(fa) * 255.0f;
        float v1 = sat01(fb) * 255.0f;
        float v2 = sat01(fc) * 255.0f;
        int i0 = min(floor_pos(v0), 255);
        int i1 = min(floor_pos(v1), 255);
        int i2 = min(floor_pos(v2), 255);
        atomicAdd(&s_cnt[base2          + i0], 1u);
        atomicAdd(&s_cnt[base2 +     NB + i1], 1u);
        atomicAdd(&s_cnt[base2 + 2 * NB + i2], 1u);
        atomicAdd(&s_sum[base2          + i0], v0);
        atomicAdd(&s_sum[base2 +     NB + i1], v1);
        atomicAdd(&s_sum[base2 + 2 * NB + i2], v2);
    }
}

__global__ void __launch_bounds__(512, 2) fused_kernel(
    const float4* __restrict__ fake, const float4* __restrict__ refb,
    const int4* __restrict__ ma, const int4* __restrict__ mb, float* out)
{
    __shared__ unsigned sh[NHIST * NB];   // hist: 24 hists | moment: cnt[3072]+sum[3072]
    __shared__ unsigned s_tots[12], s_tott[12];
    __shared__ int lutA[32], lutB[32];
    __shared__ float wsum[16];
    __shared__ int s_last;

    const int tid  = threadIdx.x;
    const int bid  = blockIdx.x;
    const int lane = tid & 31;
    const int wid  = tid >> 5;

    for (int i = tid; i < NHIST * NB; i += 512) sh[i] = 0u;
    if (tid < 32) { lutA[tid] = c_lutA[tid]; lutB[tid] = c_lutB[tid]; }
    __syncthreads();

    const int kk = bid >> 3, rr = bid & 7;
    const bool isHist = (rr < 5);

    if (isHist) {
        int rank = 5 * kk + rr;
        int stride = NHB * 512;
        for (int q = rank * 512 + tid; q < NQ; q += stride) {
            int4   a4 = ma[q],  b4 = mb[q];
            float4 f0 = fake[q], f1 = fake[q + NQ], f2 = fake[q + 2 * NQ];
            float4 r0 = refb[q], r1 = refb[q + NQ], r2 = refb[q + 2 * NQ];
            hist_px(a4.x, b4.x, f0.x, f1.x, f2.x, r0.x, r1.x, r2.x, lutA, lutB, sh);
            hist_px(a4.y, b4.y, f0.y, f1.y, f2.y, r0.y, r1.y, r2.y, lutA, lutB, sh);
            hist_px(a4.z, b4.z, f0.z, f1.z, f2.z, r0.z, r1.z, r2.z, lutA, lutB, sh);
            hist_px(a4.w, b4.w, f0.w, f1.w, f2.w, r0.w, r1.w, r2.w, lutA, lutB, sh);
        }
        __syncthreads();
        for (int i = tid; i < NHIST * NB; i += 512) {
            unsigned v = sh[i];
            if (v) atomicAdd(&g_hist[i], v);
        }
    } else {
        unsigned* s_cnt = sh;
        float*    s_sum = (float*)(sh + 12 * NB);
        int rank = 3 * kk + (rr - 5);
        int stride = NMB * 512;
        for (int q = rank * 512 + tid; q < NQ; q += stride) {
            int4   a4 = ma[q];
            float4 f0 = fake[q], f1 = fake[q + NQ], f2 = fake[q + 2 * NQ];
            mom_px(a4.x, f0.x, f1.x, f2.x, lutA, s_cnt, s_sum);
            mom_px(a4.y, f0.y, f1.y, f2.y, lutA, s_cnt, s_sum);
            mom_px(a4.z, f0.z, f1.z, f2.z, lutA, s_cnt, s_sum);
            mom_px(a4.w, f0.w, f1.w, f2.w, lutA, s_cnt, s_sum);
        }
        __syncthreads();
        for (int i = tid; i < 12 * NB; i += 512) {
            unsigned c = s_cnt[i];
            if (c) {
                atomicAdd(&g_cnt2[i], c);
                atomicAdd(&g_sum2[i], s_sum[i]);
            }
        }
    }
    __syncthreads();

    // ---- ticket: last block to flush runs the tail (no spinning anywhere)
    if (tid == 0) {
        __threadfence();
        unsigned t = atomicAdd(&g_tick, 1u);
        s_last = (t == GRID - 1) ? 1 : 0;
    }
    __syncthreads();
    if (!s_last) return;
    if (tid == 0) __threadfence();   // acquire: all flushes visible
    __syncthreads();

    // ---- tail A: 24 integer cumsums from g_hist (L2-hot), zero as we go
    unsigned* smA = sh;            // [12*NB] src cumsums -> (in place) float tables
    unsigned* smB = sh + 12 * NB;  // [12*NB] tar cumsums
    for (int task = wid; task < 24; task += 16) {
        int rc = task >> 1, side = task & 1;
        int region = rc / 3, c = rc - region * 3;
        int hbase = (region * 6 + side * 3 + c) * NB;

        unsigned v[8];
        #pragma unroll
        for (int k = 0; k < 8; k++) {
            v[k] = __ldcg(&g_hist[hbase + k * 32 + lane]);
            g_hist[hbase + k * 32 + lane] = 0u;
        }
        #pragma unroll
        for (int k = 0; k < 8; k++) {
            unsigned x = v[k];
            #pragma unroll
            for (int off = 1; off < 32; off <<= 1) {
                unsigned y = __shfl_up_sync(0xffffffffu, x, off);
                if (lane >= off) x += y;
            }
            v[k] = x;
        }
        unsigned seg[8];
        #pragma unroll
        for (int k = 0; k < 8; k++)
            seg[k] = __shfl_sync(0xffffffffu, v[k], 31);

        unsigned* dst = (side ? smB : smA) + rc * NB;
        unsigned carry = 0;
        #pragma unroll
        for (int k = 0; k < 8; k++) {
            dst[k * 32 + lane] = v[k] + carry;
            carry += seg[k];
        }
        if (lane == 0) {
            if (side) s_tott[rc] = carry; else s_tots[rc] = carry;
        }
    }
    __syncthreads();

    // ---- tail B: tables via exact integer binary lower-bound (u64 cross-mult)
    #pragma unroll
    for (int round = 0; round < 6; round++) {
        int r = round * 2 + (tid >> 8);
        int bin = tid & 255;
        const unsigned* ca = smB + r * NB;
        unsigned long long tots = s_tots[r];
        unsigned long long lhs  = (unsigned long long)smA[r * NB + bin] * s_tott[r];
        int lo = 1, hi = 255;
        #pragma unroll
        for (int s = 0; s < 8; s++) {
            int mid = (lo + hi) >> 1;
            if ((unsigned long long)ca[mid] * tots >= lhs) hi = mid; else lo = mid + 1;
        }
        bool found = (lhs >= (unsigned long long)ca[lo - 1] * tots)
                  && (lhs <= (unsigned long long)ca[lo]     * tots);
        int t = found ? lo : bin;
        if (bin == 0)   t = 0;
        if (bin == 255) t = 255;
        ((float*)smA)[r * NB + bin] = (float)t;   // in-place (sole reader/writer)
    }
    __syncthreads();

    // ---- tail C: loss = sum over 3072 bins of |sum2 - tbl*cnt2|; clean moments
    const float* tbl = (const float*)smA;
    double acc = 0.0;
    for (int i = tid; i < 12 * NB; i += 512) {
        unsigned c = g_cnt2[i];
        float    s = g_sum2[i];
        g_cnt2[i] = 0u;
        g_sum2[i] = 0.0f;
        acc += fabs((double)s - (double)tbl[i] * (double)c);
    }
    #pragma unroll
    for (int off = 16; off > 0; off >>= 1)
        acc += __shfl_down_sync(0xffffffffu, acc, off);
    if (lane == 0) wsum[wid] = (float)0.0f, ((double*)0, 0);  // placeholder avoided below
    __syncthreads();
    // block reduce in double via shared
    __shared__ double dsum[16];
    if (lane == 0) dsum[wid] = acc;
    __syncthreads();
    if (tid == 0) {
        double total = 0.0;
        #pragma unroll
        for (int i = 0; i < 16; i++) total += dsum[i];
        out[0] = (float)(total * (0.1 / 12582912.0));  // 0.1/(3*H*W)
        g_tick = 0u;
    }
    (void)wsum;
}

// ---------------------------------------------------------------- launch
extern "C" void kernel_launch(void* const* d_in, const int* in_sizes, int n_in,
                              void* d_out, int out_size)
{
    (void)in_sizes; (void)n_in; (void)out_size;
    const float4* fake = (const float4*)d_in[0];
    const float4* refb = (const float4*)d_in[1];
    const int4*   ma   = (const int4*)d_in[2];
    const int4*   mb   = (const int4*)d_in[3];
    float* out = (float*)d_out;

    fused_kernel<<<GRID, 512>>>(fake, refb, ma, mb, out);
}

// round 14
// speedup vs baseline: 2.3690x; 2.3690x over previous
#include <cuda_runtime.h>

// HMLoss: 4-region histogram-matching L1 loss, H=W=2048.
// R14: ONE kernel. Moments (cnt2/sum2 per floor-bin) accumulate inside the
// hist pass -- fake/ma are already loaded there. KEY: saturated pixels
// (v==0 or v==255 exactly; ~32% of masked) contribute ZERO loss because
// tbl[0]=0 and tbl[255]=255 are forced by the reference -> they are SKIPPED,
// eliminating the hot-address smem atomics that killed R2/R13. Interior bins
// are <0.3% dense -> conflict-free. Ticket-last block builds the 12 tables
// (R12 integer-exact tail) and reduces loss = sum_bins |sum2 - tbl*cnt2|
// (exact: sign of v-tbl uniform within a floor-bin). The 22.8us / 64MB loss
// pass is gone entirely.

#define NQ    1048576   // (2048*2048)/4
#define NB    256
#define NHIST 24
#define GRID  296
#define TPB   512
// dynamic smem layout (words): hist[6144] | cnt2[3072] | sum2(f32)[3072]
#define SM_WORDS (6144 + 3072 + 3072)

__device__ unsigned int g_hist[NHIST * NB];   // zeroed at load; self-cleaning
__device__ unsigned int g_cnt2[12 * NB];
__device__ float        g_sum2[12 * NB];
__device__ unsigned int g_tick;

// Packed label LUTs (labels 0..18).
// A: low16 = src hist base + 1 (0 = unmasked), bit16 = (label==11)
// B: low16 = tar hist base + 1 for hair/eye (0 = none), bit16 = in tar face set
__constant__ int c_lutA[32] = {
    0, 1, 3073, 4609, 3073, 4609, 0,
    1, 1, 0, 1, 1 | (1 << 16), 0, 0,
    1, 0, 0, 1537, 0,
    0,0,0,0,0,0,0,0,0,0,0,0,0
};
__constant__ int c_lutB[32] = {
    0, (1<<16), 3841, 5377, 3841, 5377, 0,
    (1<<16), (1<<16), 0, (1<<16), 0, 0, 0,
    (1<<16), 0, 0, 2305, 0,
    0,0,0,0,0,0,0,0,0,0,0,0,0
};

__device__ __forceinline__ int floor_pos(float x) {
    return __float_as_int(__fadd_rz(x, 8388608.0f)) & 0x7FFFFF;
}
__device__ __forceinline__ float sat01(float x) {
    return __saturatef(fmaf(x, 0.5f, 0.5f));
}

// ---------------- fused per-pixel: hist + loss moments ----------------
__device__ __forceinline__ void px(int la, int lb,
                                   float fa, float fb, float fc,
                                   float ra, float rb, float rc,
                                   const int* lutA, const int* lutB,
                                   unsigned* h, unsigned* cnt, float* sum)
{
    int da = lutA[la];
    int db = lutB[lb];

    // ---- src side: CDF hist + moments over mask_A regions
    int sbase = (da & 0xFFFF) - 1;
    if (sbase >= 0) {
        float s0 = sat01(fa), s1 = sat01(fb), s2 = sat01(fc);
        int b0 = min(floor_pos(s0 * 256.0f), 255);
        int b1 = min(floor_pos(s1 * 256.0f), 255);
        int b2 = min(floor_pos(s2 * 256.0f), 255);
        atomicAdd(&h[sbase          + b0], 1u);
        atomicAdd(&h[sbase +     NB + b1], 1u);
        atomicAdd(&h[sbase + 2 * NB + b2], 1u);

        // moments: skip saturated (v==0 -> |0-tbl[0]|=0; v==255 -> |255-tbl[255]|=0)
        int base2 = sbase >> 1;                  // region*3*NB
        float v0 = s0 * 255.0f, v1 = s1 * 255.0f, v2 = s2 * 255.0f;
        if (v0 != 0.0f && v0 != 255.0f) {
            int i0 = floor_pos(v0);
            atomicAdd(&cnt[base2 + i0], 1u);
            atomicAdd(&sum[base2 + i0], v0);
        }
        if (v1 != 0.0f && v1 != 255.0f) {
            int i1 = floor_pos(v1);
            atomicAdd(&cnt[base2 + NB + i1], 1u);
            atomicAdd(&sum[base2 + NB + i1], v1);
        }
        if (v2 != 0.0f && v2 != 255.0f) {
            int i2 = floor_pos(v2);
            atomicAdd(&cnt[base2 + 2 * NB + i2], 1u);
            atomicAdd(&sum[base2 + 2 * NB + i2], v2);
        }
    }

    // ---- tar side (unchanged proven body)
    int faceval = ((da >> 16) & 1) + ((db >> 16) & 1);
    int tbase = (db & 0xFFFF) - 1;
    if ((faceval | (tbase + 1)) != 0) {
        float scale = (faceval == 2) ? 512.0f : 256.0f;   // faceval==2 implies tbase<0
        int b0 = min(floor_pos(sat01(ra) * scale), 255);
        int b1 = min(floor_pos(sat01(rb) * scale), 255);
        int b2 = min(floor_pos(sat01(rc) * scale), 255);
        if (faceval > 0) {
            atomicAdd(&h[3 * NB          + b0], 1u);
            atomicAdd(&h[3 * NB +     NB + b1], 1u);
            atomicAdd(&h[3 * NB + 2 * NB + b2], 1u);
        }
        if (tbase >= 0) {
            atomicAdd(&h[tbase          + b0], 1u);
            atomicAdd(&h[tbase +     NB + b1], 1u);
            atomicAdd(&h[tbase + 2 * NB + b2], 1u);
        }
    }
}

__global__ void __launch_bounds__(TPB, 2) fused_kernel(
    const float4* __restrict__ fake, const float4* __restrict__ refb,
    const int4* __restrict__ ma, const int4* __restrict__ mb, float* out)
{
    extern __shared__ unsigned smem[];
    unsigned* h    = smem;                    // [6144] 24 hists
    unsigned* cnt  = smem + 6144;             // [3072]
    float*    sum  = (float*)(smem + 9216);   // [3072]
    __shared__ unsigned s_tots[12], s_tott[12];
    __shared__ int lutA[32], lutB[32];
    __shared__ double dsum[16];
    __shared__ int s_last;

    const int tid  = threadIdx.x;
    const int lane = tid & 31;
    const int wid  = tid >> 5;

    for (int i = tid; i < SM_WORDS; i += TPB) smem[i] = 0u;
    if (tid < 32) { lutA[tid] = c_lutA[tid]; lutB[tid] = c_lutB[tid]; }
    __syncthreads();

    // ---------------- main streaming pass ----------------
    int stride = GRID * TPB;
    for (int q = blockIdx.x * TPB + tid; q < NQ; q += stride) {
        int4   a4 = ma[q],  b4 = mb[q];
        float4 f0 = fake[q], f1 = fake[q + NQ], f2 = fake[q + 2 * NQ];
        float4 r0 = refb[q], r1 = refb[q + NQ], r2 = refb[q + 2 * NQ];
        px(a4.x, b4.x, f0.x, f1.x, f2.x, r0.x, r1.x, r2.x, lutA, lutB, h, cnt, sum);
        px(a4.y, b4.y, f0.y, f1.y, f2.y, r0.y, r1.y, r2.y, lutA, lutB, h, cnt, sum);
        px(a4.z, b4.z, f0.z, f1.z, f2.z, r0.z, r1.z, r2.z, lutA, lutB, h, cnt, sum);
        px(a4.w, b4.w, f0.w, f1.w, f2.w, r0.w, r1.w, r2.w, lutA, lutB, h, cnt, sum);
    }
    __syncthreads();

    // ---------------- flush ----------------
    for (int i = tid; i < 6144; i += TPB) {
        unsigned v = h[i];
        if (v) atomicAdd(&g_hist[i], v);
    }
    for (int i = tid; i < 3072; i += TPB) {
        unsigned c = cnt[i];
        if (c) {
            atomicAdd(&g_cnt2[i], c);
            atomicAdd(&g_sum2[i], sum[i]);
        }
    }
    __syncthreads();

    // ---------------- ticket: last block runs the tail ----------------
    if (tid == 0) {
        __threadfence();
        unsigned t = atomicAdd(&g_tick, 1u);
        s_last = (t == GRID - 1) ? 1 : 0;
    }
    __syncthreads();
    if (!s_last) return;
    if (tid == 0) __threadfence();
    __syncthreads();

    // ---- tail A: 24 integer cumsums from g_hist (L2-hot), zero as we go
    unsigned* smA = smem;            // [3072] src cumsums -> (in place) float tables
    unsigned* smB = smem + 3072;     // [3072] tar cumsums
    for (int task = wid; task < 24; task += 16) {
        int rc = task >> 1, side = task & 1;
        int region = rc / 3, c = rc - region * 3;
        int hbase = (region * 6 + side * 3 + c) * NB;

        unsigned v[8];
        #pragma unroll
        for (int k = 0; k < 8; k++) {
            v[k] = __ldcg(&g_hist[hbase + k * 32 + lane]);
            g_hist[hbase + k * 32 + lane] = 0u;
        }
        #pragma unroll
        for (int k = 0; k < 8; k++) {
            unsigned x = v[k];
            #pragma unroll
            for (int off = 1; off < 32; off <<= 1) {
                unsigned y = __shfl_up_sync(0xffffffffu, x, off);
                if (lane >= off) x += y;
            }
            v[k] = x;
        }
        unsigned seg[8];
        #pragma unroll
        for (int k = 0; k < 8; k++)
            seg[k] = __shfl_sync(0xffffffffu, v[k], 31);

        unsigned* dst = (side ? smB : smA) + rc * NB;
        unsigned carry = 0;
        #pragma unroll
        for (int k = 0; k < 8; k++) {
            dst[k * 32 + lane] = v[k] + carry;
            carry += seg[k];
        }
        if (lane == 0) {
            if (side) s_tott[rc] = carry; else s_tots[rc] = carry;
        }
    }
    __syncthreads();

    // ---- tail B: tables via exact integer binary lower-bound (u64 cross-mult)
    #pragma unroll
    for (int round = 0; round < 6; round++) {
        int r = round * 2 + (tid >> 8);
        int bin = tid & 255;
        const unsigned* ca = smB + r * NB;
        unsigned long long tots = s_tots[r];
        unsigned long long lhs  = (unsigned long long)smA[r * NB + bin] * s_tott[r];
        int lo = 1, hi = 255;
        #pragma unroll
        for (int s = 0; s < 8; s++) {
            int mid = (lo + hi) >> 1;
            if ((unsigned long long)ca[mid] * tots >= lhs) hi = mid; else lo = mid + 1;
        }
        bool found = (lhs >= (unsigned long long)ca[lo - 1] * tots)
                  && (lhs <= (unsigned long long)ca[lo]     * tots);
        int t = found ? lo : bin;
        if (bin == 0)   t = 0;
        if (bin == 255) t = 255;
        ((float*)smA)[r * NB + bin] = (float)t;   // in-place (sole reader/writer)
    }
    __syncthreads();

    // ---- tail C: loss = sum_bins |sum2 - tbl*cnt2|; clean moments for replay
    const float* tbl = (const float*)smA;
    double acc = 0.0;
    for (int i = tid; i < 3072; i += TPB) {
        unsigned c = g_cnt2[i];
        float    s = g_sum2[i];
        g_cnt2[i] = 0u;
        g_sum2[i] = 0.0f;
        acc += fabs((double)s - (double)tbl[i] * (double)c);
    }
    #pragma unroll
    for (int off = 16; off > 0; off >>= 1)
        acc += __shfl_down_sync(0xffffffffu, acc, off);
    if (lane == 0) dsum[wid] = acc;
    __syncthreads();
    if (tid == 0) {
        double total = 0.0;
        #pragma unroll
        for (int i = 0; i < 16; i++) total += dsum[i];
        out[0] = (float)(total * (0.1 / 12582912.0));  // 0.1/(3*H*W)
        g_tick = 0u;
    }
}

// ---------------------------------------------------------------- launch
extern "C" void kernel_launch(void* const* d_in, const int* in_sizes, int n_in,
                              void* d_out, int out_size)
{
    (void)in_sizes; (void)n_in; (void)out_size;
    const float4* fake = (const float4*)d_in[0];
    const float4* refb = (const float4*)d_in[1];
    const int4*   ma   = (const int4*)d_in[2];
    const int4*   mb   = (const int4*)d_in[3];
    float* out = (float*)d_out;

    cudaFuncSetAttribute(fused_kernel,
                         cudaFuncAttributeMaxDynamicSharedMemorySize,
                         SM_WORDS * 4 + 1024);
    fused_kernel<<<GRID, TPB, SM_WORDS * 4>>>(fake, refb, ma, mb, out);
}

// round 15
// speedup vs baseline: 2.5600x; 1.0806x over previous
#include <cuda_runtime.h>

// HMLoss: 4-region histogram-matching L1 loss, H=W=2048.
// R15: ONE kernel, ONE shared atomic per masked src interior channel value.
//   u64 pack: bits[50:64) cross (CDF-bin == floor-bin+1), bits[36:50) count,
//   bits[0:36) sum of v in 2^-12 units. Src CDF histogram is exactly
//   reconstructed in the tail: hist[j] = cnt[j]-cross[j]+cross[j-1]+sat.
//   Saturated values (s==0 / s==1, ~32% of masked, zero loss since tbl[0]=0,
//   tbl[255]=255) use per-lane conflict-free slot counters -> hot-bin atomic
//   serialization gone. Tar side: plain hist atomics (unchanged). Ticket-last
//   block: rebuild src hists, scan, integer-exact tables (u64 cross-mult
//   binary search), loss = sum_bins |sum - tbl*cnt|. No second pass, 128MB
//   read once, ~10.7M atomics (vs R14's 18M).

#define NQ    1048576   // (2048*2048)/4
#define NB    256
#define GRID  296
#define TPB   512
// dynamic smem: mom u64[3072] | tar u32[3072] | sat u32[768]  = 39936 bytes
#define SMEM_BYTES (3072 * 8 + 3072 * 4 + 768 * 4)
#define SMEM_W32   (SMEM_BYTES / 4)

__device__ unsigned long long g_mom[12 * NB];   // zeroed at load; self-cleaning
__device__ unsigned int       g_tar[12 * NB];
__device__ unsigned int       g_sat[768];       // [rc][side][lane]
__device__ unsigned int       g_tick;

// Packed label LUTs (labels 0..18).
// A: low16 = region*3*NB + 1 (0 = unmasked), bit16 = (label==11)
// B: low16 = tar region*3*NB + 1 for hair/eye (0 = none), bit16 = tar face set
__constant__ int c_lutA[32] = {
    0, 1, 1537, 2305, 1537, 2305, 0,
    1, 1, 0, 1, 1 | (1 << 16), 0, 0,
    1, 0, 0, 769, 0,
    0,0,0,0,0,0,0,0,0,0,0,0,0
};
__constant__ int c_lutB[32] = {
    0, (1<<16), 1537, 2305, 1537, 2305, 0,
    (1<<16), (1<<16), 0, (1<<16), 0, 0, 0,
    (1<<16), 0, 0, 769, 0,
    0,0,0,0,0,0,0,0,0,0,0,0,0
};

// floor for x in [0, 2^23): round-toward-zero add of 2^23, take mantissa bits.
__device__ __forceinline__ int floor_pos(float x) {
    return __float_as_int(__fadd_rz(x, 8388608.0f)) & 0x7FFFFF;
}
// saturate((x+1)/2)
__device__ __forceinline__ float sat01(float x) {
    return __saturatef(fmaf(x, 0.5f, 0.5f));
}

// ---- one masked src channel value: exactly ONE shared atomic ----
__device__ __forceinline__ void src_chan(float f, int idx, int lane,
                                         unsigned long long* mom, unsigned* sat)
{
    float s = sat01(f);
    int rc = idx >> 8;                       // region*3 + ch
    if (s == 0.0f) {
        atomicAdd(&sat[rc * 64 + lane], 1u);             // v==0: loss 0 (tbl[0]=0)
    } else if (s == 1.0f) {
        atomicAdd(&sat[rc * 64 + 32 + lane], 1u);        // v==255: loss 0
    } else {
        float v = s * 255.0f;                // (0,255)
        int i = floor_pos(v);                // <= 254
        int b = floor_pos(s * 256.0f);       // CDF bin, in {i, i+1}, <= 255
        unsigned vfix = (unsigned)floor_pos(v * 4096.0f);   // < 2^23
        unsigned long long pack = ((unsigned long long)(unsigned)(b - i) << 50)
                                | (1ull << 36) | (unsigned long long)vfix;
        atomicAdd(&mom[idx + i], pack);
    }
}

__device__ __forceinline__ void px(int la, int lb,
                                   float fa, float fb, float fc,
                                   float ra, float rb, float rc_,
                                   const int* lutA, const int* lutB,
                                   unsigned long long* mom, unsigned* tarh,
                                   unsigned* sat, int lane)
{
    int da = lutA[la];
    int db = lutB[lb];

    // ---- src: moments + implicit hist, one atomic per channel
    int mbase = (da & 0xFFFF) - 1;           // region*3*NB
    if (mbase >= 0) {
        src_chan(fa, mbase,          lane, mom, sat);
        src_chan(fb, mbase +     NB, lane, mom, sat);
        src_chan(fc, mbase + 2 * NB, lane, mom, sat);
    }

    // ---- tar side (proven body)
    int faceval = ((da >> 16) & 1) + ((db >> 16) & 1);
    int tbase = (db & 0xFFFF) - 1;
    if ((faceval | (tbase + 1)) != 0) {
        float scale = (faceval == 2) ? 512.0f : 256.0f;   // faceval==2 implies tbase<0
        int b0 = min(floor_pos(sat01(ra)  * scale), 255);
        int b1 = min(floor_pos(sat01(rb)  * scale), 255);
        int b2 = min(floor_pos(sat01(rc_) * scale), 255);
        if (faceval > 0) {
            atomicAdd(&tarh[b0], 1u);                      // face tar base = 0
            atomicAdd(&tarh[NB + b1], 1u);
            atomicAdd(&tarh[2 * NB + b2], 1u);
        }
        if (tbase >= 0) {
            atomicAdd(&tarh[tbase          + b0], 1u);
            atomicAdd(&tarh[tbase +     NB + b1], 1u);
            atomicAdd(&tarh[tbase + 2 * NB + b2], 1u);
        }
    }
}

__global__ void __launch_bounds__(TPB, 2) fused_kernel(
    const float4* __restrict__ fake, const float4* __restrict__ refb,
    const int4* __restrict__ ma, const int4* __restrict__ mb, float* out)
{
    extern __shared__ unsigned long long dynsm[];
    unsigned long long* mom = dynsm;                        // [3072] u64
    unsigned* tarh = (unsigned*)(dynsm + 3072);             // [3072] u32
    unsigned* sat  = tarh + 3072;                           // [768]  u32
    __shared__ int lutA[32], lutB[32];
    __shared__ unsigned s_tots[12], s_tott[12];
    __shared__ double dsum[16];
    __shared__ int s_last;

    const int tid  = threadIdx.x;
    const int lane = tid & 31;
    const int wid  = tid >> 5;

    for (int i = tid; i < SMEM_W32; i += TPB) ((unsigned*)dynsm)[i] = 0u;
    if (tid < 32) { lutA[tid] = c_lutA[tid]; lutB[tid] = c_lutB[tid]; }
    __syncthreads();

    // ---------------- single streaming pass ----------------
    int stride = GRID * TPB;
    for (int q = blockIdx.x * TPB + tid; q < NQ; q += stride) {
        int4   a4 = ma[q],  b4 = mb[q];
        float4 f0 = fake[q], f1 = fake[q + NQ], f2 = fake[q + 2 * NQ];
        float4 r0 = refb[q], r1 = refb[q + NQ], r2 = refb[q + 2 * NQ];
        px(a4.x, b4.x, f0.x, f1.x, f2.x, r0.x, r1.x, r2.x, lutA, lutB, mom, tarh, sat, lane);
        px(a4.y, b4.y, f0.y, f1.y, f2.y, r0.y, r1.y, r2.y, lutA, lutB, mom, tarh, sat, lane);
        px(a4.z, b4.z, f0.z, f1.z, f2.z, r0.z, r1.z, r2.z, lutA, lutB, mom, tarh, sat, lane);
        px(a4.w, b4.w, f0.w, f1.w, f2.w, r0.w, r1.w, r2.w, lutA, lutB, mom, tarh, sat, lane);
    }
    __syncthreads();

    // ---------------- flush ----------------
    for (int i = tid; i < 3072; i += TPB) {
        unsigned long long m = mom[i];
        if (m) atomicAdd(&g_mom[i], m);
        unsigned t = tarh[i];
        if (t) atomicAdd(&g_tar[i], t);
    }
    for (int i = tid; i < 768; i += TPB) {
        unsigned v = sat[i];
        if (v) atomicAdd(&g_sat[i], v);
    }
    __syncthreads();

    // ---------------- ticket: last block runs the tail ----------------
    if (tid == 0) {
        __threadfence();
        unsigned t = atomicAdd(&g_tick, 1u);
        s_last = (t == GRID - 1) ? 1 : 0;
    }
    __syncthreads();
    if (!s_last) return;
    if (tid == 0) __threadfence();
    __syncthreads();

    // ---- tail A: 24 cumsums; src hists reconstructed from g_mom + g_sat
    unsigned* smA = (unsigned*)dynsm;            // [3072] src cumsums -> float tables
    unsigned* smB = smA + 3072;                  // [3072] tar cumsums
    for (int task = wid; task < 24; task += 16) {
        int rc = task >> 1, side = task & 1;
        unsigned h[8];

        if (side == 0) {
            unsigned sv0 = g_sat[rc * 64 + lane];
            unsigned sv2 = g_sat[rc * 64 + 32 + lane];
            g_sat[rc * 64 + lane] = 0u;
            g_sat[rc * 64 + 32 + lane] = 0u;
            unsigned sat0   = __reduce_add_sync(0xffffffffu, sv0);
            unsigned sat255 = __reduce_add_sync(0xffffffffu, sv2);

            unsigned carrycross = 0;
            #pragma unroll
            for (int k = 0; k < 8; k++) {
                unsigned long long m = __ldcg(&g_mom[rc * NB + k * 32 + lane]);
                unsigned cnt   = (unsigned)((m >> 36) & 0x3FFFull);
                unsigned cross = (unsigned)(m >> 50);
                unsigned cm1 = __shfl_up_sync(0xffffffffu, cross, 1);
                if (lane == 0) cm1 = carrycross;
                carrycross = __shfl_sync(0xffffffffu, cross, 31);
                unsigned hv = cnt - cross + cm1;
                if (k == 0 && lane == 0)  hv += sat0;
                if (k == 7 && lane == 31) hv += sat255;
                h[k] = hv;
            }
        } else {
            #pragma unroll
            for (int k = 0; k < 8; k++) {
                h[k] = __ldcg(&g_tar[rc * NB + k * 32 + lane]);
                g_tar[rc * NB + k * 32 + lane] = 0u;
            }
        }

        // inclusive scan over 256 (8 x 5-shfl + register carry)
        #pragma unroll
        for (int k = 0; k < 8; k++) {
            unsigned x = h[k];
            #pragma unroll
            for (int off = 1; off < 32; off <<= 1) {
                unsigned y = __shfl_up_sync(0xffffffffu, x, off);
                if (lane >= off) x += y;
            }
            h[k] = x;
        }
        unsigned seg[8];
        #pragma unroll
        for (int k = 0; k < 8; k++)
            seg[k] = __shfl_sync(0xffffffffu, h[k], 31);

        unsigned* dst = (side ? smB : smA) + rc * NB;
        unsigned carry = 0;
        #pragma unroll
        for (int k = 0; k < 8; k++) {
            dst[k * 32 + lane] = h[k] + carry;
            carry += seg[k];
        }
        if (lane == 0) {
            if (side) s_tott[rc] = carry; else s_tots[rc] = carry;
        }
    }
    __syncthreads();

    // ---- tail B: tables via exact integer binary lower-bound (u64 cross-mult)
    #pragma unroll
    for (int round = 0; round < 6; round++) {
        int r = round * 2 + (tid >> 8);
        int bin = tid & 255;
        const unsigned* ca = smB + r * NB;
        unsigned long long tots = s_tots[r];
        unsigned long long lhs  = (unsigned long long)smA[r * NB + bin] * s_tott[r];
        int lo = 1, hi = 255;
        #pragma unroll
        for (int s = 0; s < 8; s++) {
            int mid = (lo + hi) >> 1;
            if ((unsigned long long)ca[mid] * tots >= lhs) hi = mid; else lo = mid + 1;
        }
        bool found = (lhs >= (unsigned long long)ca[lo - 1] * tots)
                  && (lhs <= (unsigned long long)ca[lo]     * tots);
        int t = found ? lo : bin;
        if (bin == 0)   t = 0;
        if (bin == 255) t = 255;
        ((float*)smA)[r * NB + bin] = (float)t;   // in-place (sole reader/writer)
    }
    __syncthreads();

    // ---- tail C: loss = sum_bins |sum - tbl*cnt|; clean g_mom for replay
    const float* tbl = (const float*)smA;
    double acc = 0.0;
    for (int i = tid; i < 3072; i += TPB) {
        unsigned long long m = g_mom[i];
        g_mom[i] = 0ull;
        unsigned cnt = (unsigned)((m >> 36) & 0x3FFFull);
        double sum = (double)(m & 0xFFFFFFFFFull) * (1.0 / 4096.0);
        acc += fabs(sum - (double)tbl[i] * (double)cnt);
    }
    #pragma unroll
    for (int off = 16; off > 0; off >>= 1)
        acc += __shfl_down_sync(0xffffffffu, acc, off);
    if (lane == 0) dsum[wid] = acc;
    __syncthreads();
    if (tid == 0) {
        double total = 0.0;
        #pragma unroll
        for (int i = 0; i < 16; i++) total += dsum[i];
        out[0] = (float)(total * (0.1 / 12582912.0));  // 0.1/(3*H*W)
        g_tick = 0u;
    }
}

// ---------------------------------------------------------------- launch
extern "C" void kernel_launch(void* const* d_in, const int* in_sizes, int n_in,
                              void* d_out, int out_size)
{
    (void)in_sizes; (void)n_in; (void)out_size;
    const float4* fake = (const float4*)d_in[0];
    const float4* refb = (const float4*)d_in[1];
    const int4*   ma   = (const int4*)d_in[2];
    const int4*   mb   = (const int4*)d_in[3];
    float* out = (float*)d_out;

    cudaFuncSetAttribute(fused_kernel,
                         cudaFuncAttributeMaxDynamicSharedMemorySize,
                         SMEM_BYTES);
    fused_kernel<<<GRID, TPB, SMEM_BYTES>>>(fake, refb, ma, mb, out);
}